// round 16
// baseline (speedup 1.0000x reference)
#include <cuda_runtime.h>
#include <math.h>

#define BB 8
#define NN 5000
#define NE 80000
#define MM (BB*NN)   // 40000 rows

// ---------------- scratch (static device globals; no allocations) ----------
__device__ float g_z1[MM*128];   // layer1 linear out, [N,B,128] (m = n*B+b)
__device__ float g_h1[MM*128];   // layer1 GAT out (feeds GEMM2)
__device__ float g_z2[MM*64];    // layer2 linear out
__device__ float g_el[MM];
__device__ float g_er[MM];
__device__ int   g_cnt[NN];      // zero-init; scan_k self-restores to 0
__device__ int   g_off[NN+1];
__device__ int   g_cur[NN];
__device__ int   g_csrc[NE];

// ---------------- CSR build --------------------------------------------------
__global__ void hist_k(const int* __restrict__ dst) {
    int i = blockIdx.x*blockDim.x + threadIdx.x;
    if (i < NE) atomicAdd(&g_cnt[dst[i]], 1);
}

__global__ void scan_k() {
    __shared__ int s[1024];
    int t = threadIdx.x;
    const int PER = 5;                 // 1024*5 = 5120 >= 5000
    int loc[PER];
    int sum = 0;
#pragma unroll
    for (int j = 0; j < PER; j++) {
        int idx = t*PER + j;
        int v = 0;
        if (idx < NN) { v = g_cnt[idx]; g_cnt[idx] = 0; }  // self-restore for next call
        loc[j] = sum;
        sum += v;
    }
    s[t] = sum;
    __syncthreads();
    for (int d = 1; d < 1024; d <<= 1) {
        int v = (t >= d) ? s[t-d] : 0;
        __syncthreads();
        s[t] += v;
        __syncthreads();
    }
    int excl = s[t] - sum;
#pragma unroll
    for (int j = 0; j < PER; j++) {
        int idx = t*PER + j;
        if (idx < NN) {
            int o = excl + loc[j];
            g_off[idx] = o;
            g_cur[idx] = o;
        }
    }
    if (t == 1023) g_off[NN] = s[1023];
}

__global__ void scatter_k(const int* __restrict__ src, const int* __restrict__ dst) {
    int i = blockIdx.x*blockDim.x + threadIdx.x;
    if (i < NE) {
        int d = dst[i];
        int p = atomicAdd(&g_cur[d], 1);
        g_csrc[p] = src[i];
    }
}

// ---------------- GEMM + fused attention dots --------------------------------
// Z[m,0:TN] = Xrow(m)[0:128] @ W[128,TN];
// el[m]=Z·al, er[m]=Z·ar from register accumulators.
// W is fully smem-resident (loaded once); X tiles double-buffered with register
// staging so global loads for tile kc+1 overlap the compute of tile kc.
// X tile stored TRANSPOSED (xs[k][m], stride TM+4) -> per-k A-frag = LDS.128.
// PERM: row m = n*B+b reads x at (b*NN+n)*128. Tail block clamps/predicates.
template<int TN, bool PERM>
__global__ void __launch_bounds__(256, 2) gemm_k(const float* __restrict__ X,
                                                 const float* __restrict__ W,
                                                 const float* __restrict__ al,
                                                 const float* __restrict__ ar,
                                                 float* __restrict__ Z) {
    constexpr int TM = 128, KC = 32, K = 128;
    constexpr int PW = TN + 4;            // ws row stride (floats)
    constexpr int PX = TM + 4;            // xs row stride (floats, 16B-aligned)
    extern __shared__ __align__(16) float sm[];
    float (*ws)[PW] = (float (*)[PW])sm;              // [K][PW]
    float (*xs)[PX] = (float (*)[PX])(sm + K*PW);     // [2*KC][PX]

    constexpr int CG  = TN/8;        // col groups (8 cols each)
    constexpr int RG  = 256/CG;      // row groups
    constexpr int RPT = TM/RG;       // rows per thread (8 for TN=128, 4 for TN=64)
    int t  = threadIdx.x;
    int m0 = blockIdx.x*TM;
    int cg = t % CG;
    int rg = t / CG;

    // X load slice: 4 float4 per thread per tile; row r = (t>>3)+j*32, seg = t&7
    int r_base = t >> 3;
    int seg    = t & 7;
    const float* xrow[4];
#pragma unroll
    for (int j = 0; j < 4; j++) {
        int m = m0 + r_base + j*32;
        if (m >= MM) m = MM - 1;          // tail clamp (no OOB read)
        long base;
        if (PERM) { int n = m / BB, b = m - n*BB; base = (long)(b*NN + n) * K; }
        else      { base = (long)m * K; }
        xrow[j] = X + base + seg*4;
    }

    // load ALL of W once: K x TN
#pragma unroll
    for (int i = t; i < K*(TN/4); i += 256) {
        int r = i / (TN/4), c = i % (TN/4);
        float4 v = *(const float4*)(W + (long)r*TN + c*4);
        *(float4*)&ws[r][c*4] = v;
    }

    // prologue: tile 0 -> regs -> xs buffer 0 (transposed)
    float4 xv[4];
#pragma unroll
    for (int j = 0; j < 4; j++) xv[j] = *(const float4*)(xrow[j]);
#pragma unroll
    for (int j = 0; j < 4; j++) {
        int r = r_base + j*32;
        xs[seg*4+0][r] = xv[j].x; xs[seg*4+1][r] = xv[j].y;
        xs[seg*4+2][r] = xv[j].z; xs[seg*4+3][r] = xv[j].w;
    }
    __syncthreads();

    float acc[RPT][8];
#pragma unroll
    for (int i = 0; i < RPT; i++)
#pragma unroll
        for (int j = 0; j < 8; j++) acc[i][j] = 0.f;

#pragma unroll
    for (int kc = 0; kc < K/KC; kc++) {
        // prefetch next X tile into registers (consumed after compute)
        if (kc < K/KC - 1) {
#pragma unroll
            for (int j = 0; j < 4; j++) xv[j] = *(const float4*)(xrow[j] + (kc+1)*KC);
        }
        float (*xb)[PX] = xs + (kc & 1)*KC;
#pragma unroll
        for (int k = 0; k < KC; k++) {
            float a[RPT];
#pragma unroll
            for (int i = 0; i < RPT; i += 4)
                *(float4*)&a[i] = *(const float4*)&xb[k][rg*RPT + i];
            float bb[8];
            *(float4*)&bb[0] = *(const float4*)&ws[kc*KC + k][cg*8];
            *(float4*)&bb[4] = *(const float4*)&ws[kc*KC + k][cg*8 + 4];
#pragma unroll
            for (int i = 0; i < RPT; i++)
#pragma unroll
                for (int j = 0; j < 8; j++) acc[i][j] = fmaf(a[i], bb[j], acc[i][j]);
        }
        // drain prefetch into the alternate buffer
        if (kc < K/KC - 1) {
            int bo = ((kc+1) & 1)*KC;
#pragma unroll
            for (int j = 0; j < 4; j++) {
                int r = r_base + j*32;
                xs[bo + seg*4+0][r] = xv[j].x; xs[bo + seg*4+1][r] = xv[j].y;
                xs[bo + seg*4+2][r] = xv[j].z; xs[bo + seg*4+3][r] = xv[j].w;
            }
            __syncthreads();
        }
    }

    // store Z + fused attention dot products (predicated for tail block)
    float alr[8], arr[8];
#pragma unroll
    for (int j = 0; j < 8; j++) { alr[j] = al[cg*8+j]; arr[j] = ar[cg*8+j]; }
#pragma unroll
    for (int i = 0; i < RPT; i++) {
        int m = m0 + rg*RPT + i;
        float pl = 0.f, pr = 0.f;
#pragma unroll
        for (int j = 0; j < 8; j++) {
            pl = fmaf(acc[i][j], alr[j], pl);
            pr = fmaf(acc[i][j], arr[j], pr);
        }
        // reduce across the CG lanes sharing this row (lane-aligned groups)
#pragma unroll
        for (int o = CG/2; o; o >>= 1) {
            pl += __shfl_xor_sync(0xffffffffu, pl, o);
            pr += __shfl_xor_sync(0xffffffffu, pr, o);
        }
        if (m < MM) {
            float* zp = Z + (long)m*TN + cg*8;
            float4 v0 = {acc[i][0], acc[i][1], acc[i][2], acc[i][3]};
            float4 v1 = {acc[i][4], acc[i][5], acc[i][6], acc[i][7]};
            *(float4*)zp       = v0;
            *(float4*)(zp + 4) = v1;
            if (cg == 0) {
                g_el[m] = pl;
                g_er[m] = pr;
            }
        }
    }
}

// ---------------- GAT aggregation: block per dst node, warp per batch --------
// All 8 warps of a block share node n = blockIdx.x; csrc list + per-warp edge
// scores cached in smem. FINAL: fuse final row-softmax, write d_out[(b*N+n)*64].
template<int F, bool FINAL>
__global__ void __launch_bounds__(256) agg_k(const float* __restrict__ z,
                                             const float* __restrict__ bias,
                                             float* __restrict__ out) {
    constexpr int CAP = 96;
    __shared__ int   ss[CAP];
    __shared__ float se[8][CAP];
    constexpr int C = F/32;          // features per lane (4 or 2)

    int n    = blockIdx.x;
    int t    = threadIdx.x;
    int b    = t >> 5;               // warp id == batch
    int lane = t & 31;
    int gw   = n*BB + b;
    int o0 = g_off[n], o1 = g_off[n+1];
    int deg = o1 - o0;

    if (t < deg && t < CAP) ss[t] = g_csrc[o0 + t];
    __syncthreads();

    float erb = g_er[gw];
    float mx = -1e30f;
    float acc[C], acc1[C];
#pragma unroll
    for (int c = 0; c < C; c++) { acc[c] = 0.f; acc1[c] = 0.f; }
    float denom = 0.f, d1 = 0.f;

    if (deg <= CAP) {
        // pass 1: scores -> smem, running max
        for (int i = lane; i < deg; i += 32) {
            int s = ss[i];
            float e = g_el[s*BB + b] + erb;
            e = (e > 0.f) ? e : 0.2f*e;
            se[b][i] = e;
            mx = fmaxf(mx, e);
        }
#pragma unroll
        for (int o = 16; o; o >>= 1) mx = fmaxf(mx, __shfl_xor_sync(0xffffffffu, mx, o));

        // pass 2: serial over edges (x2 unrolled), lanes parallel over features
        int i = 0;
        for (; i + 2 <= deg; i += 2) {
            int s0 = ss[i], s1 = ss[i+1];
            float ex0 = __expf(se[b][i]   - mx);
            float ex1 = __expf(se[b][i+1] - mx);
            denom += ex0; d1 += ex1;
            const float* z0 = z + (long)(s0*BB + b)*F + lane*C;
            const float* z1 = z + (long)(s1*BB + b)*F + lane*C;
            if (C == 4) {
                float4 v0 = *(const float4*)z0;
                float4 v1 = *(const float4*)z1;
                acc[0]  = fmaf(ex0, v0.x, acc[0]);  acc[1]  = fmaf(ex0, v0.y, acc[1]);
                acc[2]  = fmaf(ex0, v0.z, acc[2]);  acc[3]  = fmaf(ex0, v0.w, acc[3]);
                acc1[0] = fmaf(ex1, v1.x, acc1[0]); acc1[1] = fmaf(ex1, v1.y, acc1[1]);
                acc1[2] = fmaf(ex1, v1.z, acc1[2]); acc1[3] = fmaf(ex1, v1.w, acc1[3]);
            } else {
                float2 v0 = *(const float2*)z0;
                float2 v1 = *(const float2*)z1;
                acc[0]  = fmaf(ex0, v0.x, acc[0]);  acc[1]  = fmaf(ex0, v0.y, acc[1]);
                acc1[0] = fmaf(ex1, v1.x, acc1[0]); acc1[1] = fmaf(ex1, v1.y, acc1[1]);
            }
        }
        if (i < deg) {
            int s0 = ss[i];
            float ex0 = __expf(se[b][i] - mx);
            denom += ex0;
            const float* z0 = z + (long)(s0*BB + b)*F + lane*C;
            if (C == 4) {
                float4 v0 = *(const float4*)z0;
                acc[0] = fmaf(ex0, v0.x, acc[0]); acc[1] = fmaf(ex0, v0.y, acc[1]);
                acc[2] = fmaf(ex0, v0.z, acc[2]); acc[3] = fmaf(ex0, v0.w, acc[3]);
            } else {
                float2 v0 = *(const float2*)z0;
                acc[0] = fmaf(ex0, v0.x, acc[0]); acc[1] = fmaf(ex0, v0.y, acc[1]);
            }
        }
        denom += d1;
#pragma unroll
        for (int c = 0; c < C; c++) acc[c] += acc1[c];
    } else {
        // fallback (degree > CAP): gather path, correct for any degree
        for (int i = o0 + lane; i < o1; i += 32) {
            int s = g_csrc[i];
            float e = g_el[s*BB + b] + erb;
            e = (e > 0.f) ? e : 0.2f*e;
            mx = fmaxf(mx, e);
        }
#pragma unroll
        for (int o = 16; o; o >>= 1) mx = fmaxf(mx, __shfl_xor_sync(0xffffffffu, mx, o));
        for (int i = o0; i < o1; i++) {
            int s = g_csrc[i];
            float e = g_el[s*BB + b] + erb;
            e = (e > 0.f) ? e : 0.2f*e;
            float ex = __expf(e - mx);
            denom += ex;
            const float* zr = z + (long)(s*BB + b)*F + lane*C;
            if (C == 4) {
                float4 v = *(const float4*)zr;
                acc[0] = fmaf(ex, v.x, acc[0]); acc[1] = fmaf(ex, v.y, acc[1]);
                acc[2] = fmaf(ex, v.z, acc[2]); acc[3] = fmaf(ex, v.w, acc[3]);
            } else {
                float2 v = *(const float2*)zr;
                acc[0] = fmaf(ex, v.x, acc[0]); acc[1] = fmaf(ex, v.y, acc[1]);
            }
        }
    }

    float rd = (deg > 0) ? (1.f/denom) : 0.f;
    float ov[C];
#pragma unroll
    for (int c = 0; c < C; c++) ov[c] = acc[c]*rd + bias[lane*C + c];

    if (!FINAL) {
        float* op = out + (long)gw*F + lane*C;
        if (C == 4) { float4 v = {ov[0],ov[1],ov[2],ov[3]}; *(float4*)op = v; }
        else        { float2 v = {ov[0],ov[1]};             *(float2*)op = v; }
    } else {
        // row softmax over 64 values (2 per lane)
        float m2 = fmaxf(ov[0], ov[1]);
#pragma unroll
        for (int o = 16; o; o >>= 1) m2 = fmaxf(m2, __shfl_xor_sync(0xffffffffu, m2, o));
        float e0 = __expf(ov[0] - m2), e1 = __expf(ov[1] - m2);
        float s2 = e0 + e1;
#pragma unroll
        for (int o = 16; o; o >>= 1) s2 += __shfl_xor_sync(0xffffffffu, s2, o);
        float inv = 1.f/s2;
        float* op = out + (long)(b*NN + n)*64 + lane*2;
        float2 v = {e0*inv, e1*inv};
        *(float2*)op = v;
    }
}

// ---------------- launch -----------------------------------------------------
extern "C" void kernel_launch(void* const* d_in, const int* in_sizes, int n_in,
                              void* d_out, int out_size) {
    const float* x   = (const float*)d_in[0];
    const float* W1  = (const float*)d_in[1];
    const float* al1 = (const float*)d_in[2];
    const float* ar1 = (const float*)d_in[3];
    const float* b1  = (const float*)d_in[4];
    const float* W2  = (const float*)d_in[5];
    const float* al2 = (const float*)d_in[6];
    const float* ar2 = (const float*)d_in[7];
    const float* b2  = (const float*)d_in[8];
    const int*   src = (const int*)d_in[9];
    const int*   dst = (const int*)d_in[10];
    float* out = (float*)d_out;

    float *p_z1, *p_h1, *p_z2;
    cudaGetSymbolAddress((void**)&p_z1, g_z1);
    cudaGetSymbolAddress((void**)&p_h1, g_h1);
    cudaGetSymbolAddress((void**)&p_z2, g_z2);

    const int GEMM_GRID = (MM + 127) / 128;   // 313 — covers ALL rows (tail predicated)

    // dynamic smem sizes: ws[K][TN+4] + xs[2*KC][TM+4]  (floats)
    const int SM1 = (128*(128+4) + 64*(128+4)) * 4;   // 101376 B (TN=128)
    const int SM2 = (128*(64+4)  + 64*(128+4)) * 4;   //  68608 B (TN=64)
    cudaFuncSetAttribute(gemm_k<128, true >, cudaFuncAttributeMaxDynamicSharedMemorySize, SM1);
    cudaFuncSetAttribute(gemm_k<64,  false>, cudaFuncAttributeMaxDynamicSharedMemorySize, SM2);

    // CSR build (g_cnt self-restored to zero by scan_k each call)
    hist_k<<<(NE+255)/256, 256>>>(dst);
    scan_k<<<1, 1024>>>();
    scatter_k<<<(NE+255)/256, 256>>>(src, dst);

    // layer 1 (attn dots fused into GEMM epilogue)
    gemm_k<128, true ><<<GEMM_GRID, 256, SM1>>>(x, W1, al1, ar1, p_z1);
    agg_k <128, false><<<NN, 256>>>(p_z1, b1, p_h1);

    // layer 2 + fused final softmax
    gemm_k<64, false><<<GEMM_GRID, 256, SM2>>>(p_h1, W2, al2, ar2, p_z2);
    agg_k <64, true ><<<NN, 256>>>(p_z2, b2, out);
}

// round 17
// speedup vs baseline: 1.3045x; 1.3045x over previous
#include <cuda_runtime.h>
#include <math.h>

#define BB 8
#define NN 5000
#define NE 80000
#define MM (BB*NN)   // 40000 rows

// ---------------- scratch (static device globals; no allocations) ----------
__device__ float g_z1[MM*128];   // layer1 linear out, [N,B,128] (m = n*B+b)
__device__ float g_h1[MM*128];   // layer1 GAT out (feeds GEMM2)
__device__ float g_z2[MM*64];    // layer2 linear out
__device__ float g_el[MM];
__device__ float g_er[MM];
__device__ int   g_cnt[NN];      // zero-init; scan_k self-restores to 0
__device__ int   g_off[NN+1];
__device__ int   g_cur[NN];
__device__ int   g_csrc[NE];

// ---------------- CSR build --------------------------------------------------
__global__ void hist_k(const int* __restrict__ dst) {
    int i = blockIdx.x*blockDim.x + threadIdx.x;
    if (i < NE) atomicAdd(&g_cnt[dst[i]], 1);
}

__global__ void scan_k() {
    __shared__ int s[1024];
    int t = threadIdx.x;
    const int PER = 5;                 // 1024*5 = 5120 >= 5000
    int loc[PER];
    int sum = 0;
#pragma unroll
    for (int j = 0; j < PER; j++) {
        int idx = t*PER + j;
        int v = 0;
        if (idx < NN) { v = g_cnt[idx]; g_cnt[idx] = 0; }  // self-restore for next call
        loc[j] = sum;
        sum += v;
    }
    s[t] = sum;
    __syncthreads();
    for (int d = 1; d < 1024; d <<= 1) {
        int v = (t >= d) ? s[t-d] : 0;
        __syncthreads();
        s[t] += v;
        __syncthreads();
    }
    int excl = s[t] - sum;
#pragma unroll
    for (int j = 0; j < PER; j++) {
        int idx = t*PER + j;
        if (idx < NN) {
            int o = excl + loc[j];
            g_off[idx] = o;
            g_cur[idx] = o;
        }
    }
    if (t == 1023) g_off[NN] = s[1023];
}

__global__ void scatter_k(const int* __restrict__ src, const int* __restrict__ dst) {
    int i = blockIdx.x*blockDim.x + threadIdx.x;
    if (i < NE) {
        int d = dst[i];
        int p = atomicAdd(&g_cur[d], 1);
        g_csrc[p] = src[i];
    }
}

// ---------------- GEMM + fused attention dots (R14-proven structure) ---------
// Z[m,0:TN] = Xrow(m)[0:128] @ W[128,TN];
// el[m]=Z·al, er[m]=Z·ar from register accumulators.
// X tile stored TRANSPOSED in smem (xs[k][m]) -> per-k A-frag = LDS.128.
// PERM: row m = n*B+b reads x at (b*NN+n)*128. Tail block clamps/predicates.
template<int TM, int TN, bool PERM>
__global__ void __launch_bounds__(256) gemm_k(const float* __restrict__ X,
                                              const float* __restrict__ W,
                                              const float* __restrict__ al,
                                              const float* __restrict__ ar,
                                              float* __restrict__ Z) {
    constexpr int KC = 32, K = 128;
    __shared__ __align__(16) float xs[KC][TM+4];   // transposed X tile
    __shared__ __align__(16) float ws[KC][TN+4];
    constexpr int CG  = TN/8;        // col groups (8 cols each)
    constexpr int RG  = 256/CG;      // row groups
    constexpr int RPT = TM/RG;       // rows per thread (8 for both gemm1/gemm2)
    int t  = threadIdx.x;
    int m0 = blockIdx.x*TM;
    int cg = t % CG;
    int rg = t / CG;

    float acc[RPT][8];
#pragma unroll
    for (int i = 0; i < RPT; i++)
#pragma unroll
        for (int j = 0; j < 8; j++) acc[i][j] = 0.f;

    for (int kc = 0; kc < K; kc += KC) {
        // load X tile: TM rows x KC cols, 8 threads/row, float4 each;
        // store transposed (scalar STS x4, bounded bank conflicts)
#pragma unroll
        for (int i = t; i < TM*8; i += 256) {
            int r = i >> 3, seg = i & 7;
            int m = m0 + r;
            if (m >= MM) m = MM - 1;          // tail clamp (no OOB read)
            long base;
            if (PERM) { int n = m / BB, b = m - n*BB; base = (long)(b*NN + n) * K; }
            else      { base = (long)m * K; }
            float4 v = *(const float4*)(X + base + kc + seg*4);
            xs[seg*4+0][r] = v.x; xs[seg*4+1][r] = v.y;
            xs[seg*4+2][r] = v.z; xs[seg*4+3][r] = v.w;
        }
        // load W tile: KC x TN
#pragma unroll
        for (int i = t; i < KC*(TN/4); i += 256) {
            int r = i / (TN/4), c = i % (TN/4);
            float4 v = *(const float4*)(W + (kc + r)*TN + c*4);
            *(float4*)&ws[r][c*4] = v;
        }
        __syncthreads();
#pragma unroll
        for (int k = 0; k < KC; k++) {
            float a[RPT];
#pragma unroll
            for (int i = 0; i < RPT; i += 4)
                *(float4*)&a[i] = *(const float4*)&xs[k][rg*RPT + i];
            float bb[8];
            *(float4*)&bb[0] = *(const float4*)&ws[k][cg*8];
            *(float4*)&bb[4] = *(const float4*)&ws[k][cg*8 + 4];
#pragma unroll
            for (int i = 0; i < RPT; i++)
#pragma unroll
                for (int j = 0; j < 8; j++) acc[i][j] = fmaf(a[i], bb[j], acc[i][j]);
        }
        __syncthreads();
    }
    // store Z + fused attention dot products (predicated for tail block)
    float alr[8], arr[8];
#pragma unroll
    for (int j = 0; j < 8; j++) { alr[j] = al[cg*8+j]; arr[j] = ar[cg*8+j]; }
#pragma unroll
    for (int i = 0; i < RPT; i++) {
        int m = m0 + rg*RPT + i;
        float pl = 0.f, pr = 0.f;
#pragma unroll
        for (int j = 0; j < 8; j++) {
            pl = fmaf(acc[i][j], alr[j], pl);
            pr = fmaf(acc[i][j], arr[j], pr);
        }
        // reduce across the CG lanes sharing this row (lane-aligned groups)
#pragma unroll
        for (int o = CG/2; o; o >>= 1) {
            pl += __shfl_xor_sync(0xffffffffu, pl, o);
            pr += __shfl_xor_sync(0xffffffffu, pr, o);
        }
        if (m < MM) {
            float* zp = Z + (long)m*TN + cg*8;
            float4 v0 = {acc[i][0], acc[i][1], acc[i][2], acc[i][3]};
            float4 v1 = {acc[i][4], acc[i][5], acc[i][6], acc[i][7]};
            *(float4*)zp       = v0;
            *(float4*)(zp + 4) = v1;
            if (cg == 0) {
                g_el[m] = pl;
                g_er[m] = pr;
            }
        }
    }
}

// ---------------- GAT aggregation: block per dst node, warp per batch --------
// All 8 warps of a block share node n = blockIdx.x; csrc list + per-warp edge
// scores cached in smem. Pass 2 unrolled x4 (MLP=4 on z gathers).
// FINAL: fuse final row-softmax, write d_out[(b*N+n)*64].
template<int F, bool FINAL>
__global__ void __launch_bounds__(256) agg_k(const float* __restrict__ z,
                                             const float* __restrict__ bias,
                                             float* __restrict__ out) {
    constexpr int CAP = 96;
    __shared__ int   ss[CAP];
    __shared__ float se[8][CAP];
    constexpr int C = F/32;          // features per lane (4 or 2)

    int n    = blockIdx.x;
    int t    = threadIdx.x;
    int b    = t >> 5;               // warp id == batch
    int lane = t & 31;
    int gw   = n*BB + b;
    int o0 = g_off[n], o1 = g_off[n+1];
    int deg = o1 - o0;

    if (t < deg && t < CAP) ss[t] = g_csrc[o0 + t];
    __syncthreads();

    float erb = g_er[gw];
    float mx = -1e30f;
    float acc[C], acc1[C];
#pragma unroll
    for (int c = 0; c < C; c++) { acc[c] = 0.f; acc1[c] = 0.f; }
    float denom = 0.f, d1 = 0.f;

    if (deg <= CAP) {
        // pass 1: scores -> smem, running max
        for (int i = lane; i < deg; i += 32) {
            int s = ss[i];
            float e = g_el[s*BB + b] + erb;
            e = (e > 0.f) ? e : 0.2f*e;
            se[b][i] = e;
            mx = fmaxf(mx, e);
        }
#pragma unroll
        for (int o = 16; o; o >>= 1) mx = fmaxf(mx, __shfl_xor_sync(0xffffffffu, mx, o));

        // pass 2: serial over edges, x4 unrolled (4 loads in flight), lanes
        // parallel over features
        int i = 0;
        for (; i + 4 <= deg; i += 4) {
            int s0 = ss[i], s1 = ss[i+1], s2 = ss[i+2], s3 = ss[i+3];
            float ex0 = __expf(se[b][i]   - mx);
            float ex1 = __expf(se[b][i+1] - mx);
            float ex2 = __expf(se[b][i+2] - mx);
            float ex3 = __expf(se[b][i+3] - mx);
            denom += ex0 + ex2; d1 += ex1 + ex3;
            const float* z0 = z + (long)(s0*BB + b)*F + lane*C;
            const float* z1 = z + (long)(s1*BB + b)*F + lane*C;
            const float* z2 = z + (long)(s2*BB + b)*F + lane*C;
            const float* z3 = z + (long)(s3*BB + b)*F + lane*C;
            if (C == 4) {
                float4 v0 = *(const float4*)z0;
                float4 v1 = *(const float4*)z1;
                float4 v2 = *(const float4*)z2;
                float4 v3 = *(const float4*)z3;
                acc[0]  = fmaf(ex0, v0.x, acc[0]);  acc[1]  = fmaf(ex0, v0.y, acc[1]);
                acc[2]  = fmaf(ex0, v0.z, acc[2]);  acc[3]  = fmaf(ex0, v0.w, acc[3]);
                acc1[0] = fmaf(ex1, v1.x, acc1[0]); acc1[1] = fmaf(ex1, v1.y, acc1[1]);
                acc1[2] = fmaf(ex1, v1.z, acc1[2]); acc1[3] = fmaf(ex1, v1.w, acc1[3]);
                acc[0]  = fmaf(ex2, v2.x, acc[0]);  acc[1]  = fmaf(ex2, v2.y, acc[1]);
                acc[2]  = fmaf(ex2, v2.z, acc[2]);  acc[3]  = fmaf(ex2, v2.w, acc[3]);
                acc1[0] = fmaf(ex3, v3.x, acc1[0]); acc1[1] = fmaf(ex3, v3.y, acc1[1]);
                acc1[2] = fmaf(ex3, v3.z, acc1[2]); acc1[3] = fmaf(ex3, v3.w, acc1[3]);
            } else {
                float2 v0 = *(const float2*)z0;
                float2 v1 = *(const float2*)z1;
                float2 v2 = *(const float2*)z2;
                float2 v3 = *(const float2*)z3;
                acc[0]  = fmaf(ex0, v0.x, acc[0]);  acc[1]  = fmaf(ex0, v0.y, acc[1]);
                acc1[0] = fmaf(ex1, v1.x, acc1[0]); acc1[1] = fmaf(ex1, v1.y, acc1[1]);
                acc[0]  = fmaf(ex2, v2.x, acc[0]);  acc[1]  = fmaf(ex2, v2.y, acc[1]);
                acc1[0] = fmaf(ex3, v3.x, acc1[0]); acc1[1] = fmaf(ex3, v3.y, acc1[1]);
            }
        }
        for (; i < deg; i++) {
            int s0 = ss[i];
            float ex0 = __expf(se[b][i] - mx);
            denom += ex0;
            const float* z0 = z + (long)(s0*BB + b)*F + lane*C;
            if (C == 4) {
                float4 v0 = *(const float4*)z0;
                acc[0] = fmaf(ex0, v0.x, acc[0]); acc[1] = fmaf(ex0, v0.y, acc[1]);
                acc[2] = fmaf(ex0, v0.z, acc[2]); acc[3] = fmaf(ex0, v0.w, acc[3]);
            } else {
                float2 v0 = *(const float2*)z0;
                acc[0] = fmaf(ex0, v0.x, acc[0]); acc[1] = fmaf(ex0, v0.y, acc[1]);
            }
        }
        denom += d1;
#pragma unroll
        for (int c = 0; c < C; c++) acc[c] += acc1[c];
    } else {
        // fallback (degree > CAP): gather path, correct for any degree
        for (int i = o0 + lane; i < o1; i += 32) {
            int s = g_csrc[i];
            float e = g_el[s*BB + b] + erb;
            e = (e > 0.f) ? e : 0.2f*e;
            mx = fmaxf(mx, e);
        }
#pragma unroll
        for (int o = 16; o; o >>= 1) mx = fmaxf(mx, __shfl_xor_sync(0xffffffffu, mx, o));
        for (int i = o0; i < o1; i++) {
            int s = g_csrc[i];
            float e = g_el[s*BB + b] + erb;
            e = (e > 0.f) ? e : 0.2f*e;
            float ex = __expf(e - mx);
            denom += ex;
            const float* zr = z + (long)(s*BB + b)*F + lane*C;
            if (C == 4) {
                float4 v = *(const float4*)zr;
                acc[0] = fmaf(ex, v.x, acc[0]); acc[1] = fmaf(ex, v.y, acc[1]);
                acc[2] = fmaf(ex, v.z, acc[2]); acc[3] = fmaf(ex, v.w, acc[3]);
            } else {
                float2 v = *(const float2*)zr;
                acc[0] = fmaf(ex, v.x, acc[0]); acc[1] = fmaf(ex, v.y, acc[1]);
            }
        }
    }

    float rd = (deg > 0) ? (1.f/denom) : 0.f;
    float ov[C];
#pragma unroll
    for (int c = 0; c < C; c++) ov[c] = acc[c]*rd + bias[lane*C + c];

    if (!FINAL) {
        float* op = out + (long)gw*F + lane*C;
        if (C == 4) { float4 v = {ov[0],ov[1],ov[2],ov[3]}; *(float4*)op = v; }
        else        { float2 v = {ov[0],ov[1]};             *(float2*)op = v; }
    } else {
        // row softmax over 64 values (2 per lane)
        float m2 = fmaxf(ov[0], ov[1]);
#pragma unroll
        for (int o = 16; o; o >>= 1) m2 = fmaxf(m2, __shfl_xor_sync(0xffffffffu, m2, o));
        float e0 = __expf(ov[0] - m2), e1 = __expf(ov[1] - m2);
        float s2 = e0 + e1;
#pragma unroll
        for (int o = 16; o; o >>= 1) s2 += __shfl_xor_sync(0xffffffffu, s2, o);
        float inv = 1.f/s2;
        float* op = out + (long)(b*NN + n)*64 + lane*2;
        float2 v = {e0*inv, e1*inv};
        *(float2*)op = v;
    }
}

// ---------------- launch -----------------------------------------------------
extern "C" void kernel_launch(void* const* d_in, const int* in_sizes, int n_in,
                              void* d_out, int out_size) {
    const float* x   = (const float*)d_in[0];
    const float* W1  = (const float*)d_in[1];
    const float* al1 = (const float*)d_in[2];
    const float* ar1 = (const float*)d_in[3];
    const float* b1  = (const float*)d_in[4];
    const float* W2  = (const float*)d_in[5];
    const float* al2 = (const float*)d_in[6];
    const float* ar2 = (const float*)d_in[7];
    const float* b2  = (const float*)d_in[8];
    const int*   src = (const int*)d_in[9];
    const int*   dst = (const int*)d_in[10];
    float* out = (float*)d_out;

    float *p_z1, *p_h1, *p_z2;
    cudaGetSymbolAddress((void**)&p_z1, g_z1);
    cudaGetSymbolAddress((void**)&p_h1, g_h1);
    cudaGetSymbolAddress((void**)&p_z2, g_z2);

    const int GRID1 = (MM + 127) / 128;   // TM=128
    const int GRID2 = (MM + 255) / 256;   // TM=256

    // CSR build (g_cnt self-restored to zero by scan_k each call)
    hist_k<<<(NE+255)/256, 256>>>(dst);
    scan_k<<<1, 1024>>>();
    scatter_k<<<(NE+255)/256, 256>>>(src, dst);

    // layer 1 (attn dots fused into GEMM epilogue)
    gemm_k<128, 128, true ><<<GRID1, 256>>>(x, W1, al1, ar1, p_z1);
    agg_k <128, false><<<NN, 256>>>(p_z1, b1, p_h1);

    // layer 2 + fused final softmax
    gemm_k<256, 64, false><<<GRID2, 256>>>(p_h1, W2, al2, ar2, p_z2);
    agg_k <64, true ><<<NN, 256>>>(p_z2, b2, out);
}